// round 16
// baseline (speedup 1.0000x reference)
#include <cuda_runtime.h>
#include <cuda_bf16.h>
#include <cuda_fp16.h>
#include <cstdint>

#define D_MODEL 1024
#define N_HEAD  16
#define HEAD_DIM 64
#define BATCH   4
#define SEQ     2048
#define BH      (BATCH * N_HEAD)          // 64
#define MROWS   (BATCH * SEQ)             // 8192
#define GK      1024
#define GN      1024

// ---------------------------------------------------------------------------
// Scratch (device globals)
// ---------------------------------------------------------------------------
__device__ __half g_q16[MROWS * D_MODEL], g_k16[MROWS * D_MODEL], g_v16[MROWS * D_MODEL];
__device__ __half g_af[MROWS * D_MODEL];     // flash output, fp16
// projected Q/K/V single fp16, heads layout [bh][s][hd]
// (Q pre-scaled by log2(e)/32 -> scores are base-2 logits)
__device__ __half g_Q16[BH * SEQ * HEAD_DIM], g_K16[BH * SEQ * HEAD_DIM];
__device__ __half g_V16[BH * SEQ * HEAD_DIM];
// transposed weights [N][K], single fp16
__device__ __half g_Wq16[D_MODEL * D_MODEL], g_Wk16[D_MODEL * D_MODEL];
__device__ __half g_Wv16[D_MODEL * D_MODEL], g_Wo16[D_MODEL * D_MODEL];

// ---------------------------------------------------------------------------
__device__ __forceinline__ uint32_t smem_u32(const void* p) {
    uint32_t a;
    asm("{ .reg .u64 t; cvta.to.shared.u64 t, %1; cvt.u32.u64 %0, t; }"
        : "=r"(a) : "l"(p));
    return a;
}

#define CP_ASYNC16(dst_u32, src_ptr) \
    asm volatile("cp.async.cg.shared.global [%0], [%1], 16;" \
        :: "r"(dst_u32), "l"(src_ptr))

__device__ __forceinline__ void ldsm_x4(uint32_t* r, uint32_t addr) {
    asm volatile("ldmatrix.sync.aligned.m8n8.x4.shared.b16 {%0,%1,%2,%3}, [%4];"
        : "=r"(r[0]), "=r"(r[1]), "=r"(r[2]), "=r"(r[3]) : "r"(addr));
}

__device__ __forceinline__ void ldsm_x4_t(uint32_t* r, uint32_t addr) {
    asm volatile("ldmatrix.sync.aligned.m8n8.x4.trans.shared.b16 {%0,%1,%2,%3}, [%4];"
        : "=r"(r[0]), "=r"(r[1]), "=r"(r[2]), "=r"(r[3]) : "r"(addr));
}

__device__ __forceinline__ void mma16816h(float* d, const uint32_t* a,
                                          const uint32_t* b) {
    asm volatile(
        "mma.sync.aligned.m16n8k16.row.col.f32.f16.f16.f32 "
        "{%0,%1,%2,%3}, {%4,%5,%6,%7}, {%8,%9}, {%0,%1,%2,%3};"
        : "+f"(d[0]), "+f"(d[1]), "+f"(d[2]), "+f"(d[3])
        : "r"(a[0]), "r"(a[1]), "r"(a[2]), "r"(a[3]), "r"(b[0]), "r"(b[1]));
}

__device__ __forceinline__ uint32_t ex2_f16x2(uint32_t x) {
    uint32_t r;
    asm("ex2.approx.f16x2 %0, %1;" : "=r"(r) : "r"(x));
    return r;
}

// ---------------------------------------------------------------------------
// fp16 single-term GEMM: C = A * W + bias.  256 threads, BM=128 BN=128 BK=32,
// 4-stage cp.async pipeline, 81.9 KB smem -> 2 CTAs/SM.
// Round-14 loop structure (issue-before-wait; two barriers) — fastest measured.
// MODE 1: single fp16 heads layout out (z==0 scales by log2e/32).
// MODE 0: fp32 row-major out.
// ---------------------------------------------------------------------------
#define NSLABS  32
#define S_A     (128 * 40)
#define S_ST    (2 * S_A)
#define G4_SMEM (4 * S_ST * 2)            // 81920

template <int MODE>
__global__ void __launch_bounds__(256) gemm_mma_kernel(
    const __half* __restrict__ A0, const __half* __restrict__ A1,
    const __half* __restrict__ A2,
    const __half* __restrict__ B0, const __half* __restrict__ B1,
    const __half* __restrict__ B2,
    const float* __restrict__ bias0, const float* __restrict__ bias1,
    const float* __restrict__ bias2,
    __half* __restrict__ O0, __half* __restrict__ O1,
    __half* __restrict__ O2,
    float* __restrict__ out32)
{
    extern __shared__ __half gsm[];

    const int z = blockIdx.z;
    const __half* Ag = (z == 0) ? A0 : (z == 1) ? A1 : A2;
    const __half* Bg = (z == 0) ? B0 : (z == 1) ? B1 : B2;
    const float* bias = (z == 0) ? bias0 : (z == 1) ? bias1 : bias2;
    __half* outp = (z == 0) ? O0 : (z == 1) ? O1 : O2;
    const float oscale = (MODE == 1 && z == 0) ? 0.03125f * 1.4426950408889634f
                                               : 1.0f;

    const int tid = threadIdx.x;
    const int wid = tid >> 5;
    const int lane = tid & 31;
    const int m0 = blockIdx.y * 128;
    const int n0 = blockIdx.x * 128;
    const int wm = (wid & 1) * 64;
    const int wn = (wid >> 1) * 32;

    float acc[4][4][4];
#pragma unroll
    for (int i = 0; i < 4; i++)
#pragma unroll
        for (int j = 0; j < 4; j++)
#pragma unroll
            for (int c = 0; c < 4; c++) acc[i][j][c] = 0.f;

    const int ldrow = tid >> 2;
    const int ldcol = (tid & 3) * 8;

    auto issue_load = [&](int stage, int slab) {
        const int k0 = slab << 5;
        __half* sA = gsm + stage * S_ST;
        __half* sB = sA + S_A;
#pragma unroll
        for (int r = 0; r < 2; r++) {
            const int row = ldrow + r * 64;
            const size_t ga = (size_t)(m0 + row) * GK + k0 + ldcol;
            const size_t gb = (size_t)(n0 + row) * GK + k0 + ldcol;
            CP_ASYNC16(smem_u32(&sA[row * 40 + ldcol]), Ag + ga);
            CP_ASYNC16(smem_u32(&sB[row * 40 + ldcol]), Bg + gb);
        }
        asm volatile("cp.async.commit_group;" ::: "memory");
    };

    issue_load(0, 0);
    issue_load(1, 1);
    issue_load(2, 2);

    int st = 0;
    for (int i = 0; i < NSLABS; i++) {
        if (i + 3 < NSLABS) {
            issue_load((st + 3) & 3, i + 3);
            asm volatile("cp.async.wait_group 3;" ::: "memory");
        } else if (i + 2 < NSLABS) {
            asm volatile("cp.async.wait_group 2;" ::: "memory");
        } else if (i + 1 < NSLABS) {
            asm volatile("cp.async.wait_group 1;" ::: "memory");
        } else {
            asm volatile("cp.async.wait_group 0;" ::: "memory");
        }
        __syncthreads();

        const __half* sA = gsm + st * S_ST;
        const __half* sB = sA + S_A;

#pragma unroll
        for (int ks = 0; ks < 2; ks++) {
            uint32_t bf[4][2];
#pragma unroll
            for (int njp = 0; njp < 2; njp++) {
                const int t = lane >> 3;
                const int sof = (wn + njp * 16 + (t >> 1) * 8 + (lane & 7)) * 40 +
                                ks * 16 + (t & 1) * 8;
                uint32_t r[4];
                ldsm_x4(r, smem_u32(&sB[sof]));
                bf[njp * 2 + 0][0] = r[0]; bf[njp * 2 + 0][1] = r[1];
                bf[njp * 2 + 1][0] = r[2]; bf[njp * 2 + 1][1] = r[3];
            }
#pragma unroll
            for (int mi = 0; mi < 4; mi++) {
                uint32_t af[4];
                const int sof = (wm + mi * 16 + (lane & 15)) * 40 +
                                ks * 16 + (lane >> 4) * 8;
                ldsm_x4(af, smem_u32(&sA[sof]));
#pragma unroll
                for (int nj = 0; nj < 4; nj++)
                    mma16816h(acc[mi][nj], af, bf[nj]);
            }
        }
        __syncthreads();
        st = (st + 1) & 3;
    }

#pragma unroll
    for (int mi = 0; mi < 4; mi++) {
#pragma unroll
        for (int nj = 0; nj < 4; nj++) {
            const int n = n0 + wn + nj * 8 + (lane & 3) * 2;
            const float b0 = bias[n], b1 = bias[n + 1];
#pragma unroll
            for (int half = 0; half < 2; half++) {
                const int m = m0 + wm + mi * 16 + (lane >> 2) + half * 8;
                const float v0 = (acc[mi][nj][half * 2 + 0] + b0) * oscale;
                const float v1 = (acc[mi][nj][half * 2 + 1] + b1) * oscale;
                if (MODE == 1) {
                    const int b = m >> 11;
                    const int s = m & (SEQ - 1);
                    const int h = n >> 6;
                    const int d = n & 63;
                    const size_t idx =
                        ((((size_t)b * N_HEAD + h) * SEQ) + s) * HEAD_DIM + d;
                    *(__half2*)&outp[idx] = __floats2half2_rn(v0, v1);
                } else {
                    *(float2*)&out32[(size_t)m * GN + n] = make_float2(v0, v1);
                }
            }
        }
    }
}

// ---------------------------------------------------------------------------
// Fused flash attention, all-fp16.  128-key KV stages (double-buffered),
// two 64-key compute passes per stage -> half the barriers/waits per key.
// exp2-domain softmax, f16x2 EX2 tail, heavy CTAs first, masked-warp skip.
// smem: Q 128x72 + 2 stages x (K 128x72 + V 128x72) = 92160 B.
// grid (SEQ/128, BH), 256 threads.
// ---------------------------------------------------------------------------
#define FPAD 72
#define KV_ST (2 * 128 * FPAD)           // K+V per stage (elements)
#define FLASH_SMEM ((128 * FPAD + 2 * KV_ST) * 2)   // 92160

__global__ void __launch_bounds__(256) flash_kernel(
    const __half* __restrict__ Qg, const __half* __restrict__ Kg,
    const __half* __restrict__ Vg, __half* __restrict__ Oa)
{
    extern __shared__ __half fsm[];
    __half* sQ = fsm;                        // 128*FPAD
    __half* kvBase = sQ + 128 * FPAD;        // 2 stages of [K 128x72 | V 128x72]

    const int tid = threadIdx.x;
    const int wid = tid >> 5;
    const int lane = tid & 31;
    // reversed order: heavy causal tiles (large i0) first
    const int i0 = (gridDim.x - 1 - blockIdx.x) * 128;
    const int bh = blockIdx.y;
    const size_t base = (size_t)bh * SEQ * HEAD_DIM;

    for (int c = tid; c < 1024; c += 256) {
        const int row = c >> 3, c8 = (c & 7) * 8;
        *(uint4*)&sQ[row * FPAD + c8] =
            *(const uint4*)&Qg[base + (size_t)(i0 + row) * HEAD_DIM + c8];
    }

    // loader: 128 rows x 64 halfs per matrix; thread covers row=tid>>1,
    // 4 chunks of 8 halfs at cols (tid&1)*32 + r*8
    const int ldrow = tid >> 1;              // 0..127
    const int ldcb = (tid & 1) * 32;         // 0 or 32

    auto issue_kv = [&](int it2, int buf) {
        const int kk0 = it2 * 128;
        __half* sK = kvBase + buf * KV_ST;
        __half* sV = sK + 128 * FPAD;
        const size_t gr = base + (size_t)(kk0 + ldrow) * HEAD_DIM;
#pragma unroll
        for (int r = 0; r < 4; r++) {
            const int col = ldcb + r * 8;
            CP_ASYNC16(smem_u32(&sK[ldrow * FPAD + col]), Kg + gr + col);
            CP_ASYNC16(smem_u32(&sV[ldrow * FPAD + col]), Vg + gr + col);
        }
        asm volatile("cp.async.commit_group;" ::: "memory");
    };

    float oacc[8][4];
#pragma unroll
    for (int nt = 0; nt < 8; nt++)
#pragma unroll
        for (int c = 0; c < 4; c++) oacc[nt][c] = 0.f;
    float mrow[2] = {-1e30f, -1e30f};
    float lrow[2] = {0.f, 0.f};

    const int r0 = lane >> 2;
    const int nIter2 = i0 / 128 + 1;     // 128-key stages; covers keys <= i0+127

    issue_kv(0, 0);

    for (int it2 = 0; it2 < nIter2; it2++) {
        asm volatile("cp.async.wait_group 0;" ::: "memory");
        __syncthreads();
        if (it2 + 1 < nIter2) issue_kv(it2 + 1, (it2 + 1) & 1);

        const __half* sKst = kvBase + (it2 & 1) * KV_ST;
        const __half* sVst = sKst + 128 * FPAD;

#pragma unroll
        for (int sub = 0; sub < 2; sub++) {
            const int kk0 = it2 * 128 + sub * 64;
            // warp fully masked? (all 16 rows < kk0) -> skip compute
            if (kk0 > i0 + wid * 16 + 15) continue;

            const __half* sK = sKst + sub * 64 * FPAD;
            const __half* sV = sVst + sub * 64 * FPAD;

            // ---- S = Q K^T (base-2 logits; Q pre-scaled) ----
            float sacc[8][4];
#pragma unroll
            for (int nt = 0; nt < 8; nt++)
#pragma unroll
                for (int c = 0; c < 4; c++) sacc[nt][c] = 0.f;

#pragma unroll
            for (int ks = 0; ks < 4; ks++) {
                uint32_t af[4];
                const int qof = (wid * 16 + (lane & 15)) * FPAD +
                                ks * 16 + (lane >> 4) * 8;
                ldsm_x4(af, smem_u32(&sQ[qof]));
                uint32_t bf[8][2];
#pragma unroll
                for (int njp = 0; njp < 4; njp++) {
                    const int t = lane >> 3;
                    const int kof = (njp * 16 + (t >> 1) * 8 + (lane & 7)) * FPAD +
                                    ks * 16 + (t & 1) * 8;
                    uint32_t r[4];
                    ldsm_x4(r, smem_u32(&sK[kof]));
                    bf[njp * 2 + 0][0] = r[0]; bf[njp * 2 + 0][1] = r[1];
                    bf[njp * 2 + 1][0] = r[2]; bf[njp * 2 + 1][1] = r[3];
                }
#pragma unroll
                for (int nt = 0; nt < 8; nt++)
                    mma16816h(sacc[nt], af, bf[nt]);
            }

            // ---- causal mask + running max ----
            const bool domask = (kk0 + 63 > i0 + wid * 16);
            float tmax[2] = {-1e30f, -1e30f};
#pragma unroll
            for (int nt = 0; nt < 8; nt++) {
#pragma unroll
                for (int c = 0; c < 4; c++) {
                    float s = sacc[nt][c];
                    if (domask) {
                        const int gi = i0 + wid * 16 + r0 + (c >> 1) * 8;
                        const int gj = kk0 + nt * 8 + (lane & 3) * 2 + (c & 1);
                        if (gj > gi) s = -1e30f;
                    }
                    sacc[nt][c] = s;
                    tmax[c >> 1] = fmaxf(tmax[c >> 1], s);
                }
            }
#pragma unroll
            for (int h2 = 0; h2 < 2; h2++) {
                tmax[h2] = fmaxf(tmax[h2], __shfl_xor_sync(0xffffffffu, tmax[h2], 1));
                tmax[h2] = fmaxf(tmax[h2], __shfl_xor_sync(0xffffffffu, tmax[h2], 2));
            }
            float fac[2], mnew[2];
#pragma unroll
            for (int h2 = 0; h2 < 2; h2++) {
                mnew[h2] = fmaxf(mrow[h2], tmax[h2]);
                fac[h2] = exp2f(mrow[h2] - mnew[h2]);
                mrow[h2] = mnew[h2];
                lrow[h2] *= fac[h2];
            }
            if (__any_sync(0xffffffffu, (fac[0] != 1.f) | (fac[1] != 1.f))) {
#pragma unroll
                for (int nt = 0; nt < 8; nt++)
#pragma unroll
                    for (int c = 0; c < 4; c++) oacc[nt][c] *= fac[c >> 1];
            }

            // ---- p = exp2(s - mnew): fp32 diff, f16x2 EX2 -> PV A-frag ----
            uint32_t pf[4][4];
            __half2 lsum[2];
            lsum[0] = __floats2half2_rn(0.f, 0.f);
            lsum[1] = __floats2half2_rn(0.f, 0.f);
#pragma unroll
            for (int t = 0; t < 4; t++) {
#pragma unroll
                for (int q = 0; q < 4; q++) {
                    const int nt = 2 * t + (q >> 1);
                    const int hh = q & 1;
                    const float da = sacc[nt][hh * 2 + 0] - mnew[hh];
                    const float db = sacc[nt][hh * 2 + 1] - mnew[hh];
                    const __half2 dh = __floats2half2_rn(da, db);
                    const uint32_t ph = ex2_f16x2(*(const uint32_t*)&dh);
                    pf[t][q] = ph;
                    lsum[hh] = __hadd2(lsum[hh], *(const __half2*)&ph);
                }
            }
#pragma unroll
            for (int h2 = 0; h2 < 2; h2++) {
                const float2 lf = __half22float2(lsum[h2]);
                lrow[h2] += lf.x + lf.y;
            }

            // ---- O += P V ----
#pragma unroll
            for (int ks = 0; ks < 4; ks++) {
                uint32_t bf[8][2];
#pragma unroll
                for (int njp = 0; njp < 4; njp++) {
                    const int t = lane >> 3;
                    const int vof = (ks * 16 + (t & 1) * 8 + (lane & 7)) * FPAD +
                                    njp * 16 + (t >> 1) * 8;
                    uint32_t r[4];
                    ldsm_x4_t(r, smem_u32(&sV[vof]));
                    bf[njp * 2 + 0][0] = r[0]; bf[njp * 2 + 0][1] = r[1];
                    bf[njp * 2 + 1][0] = r[2]; bf[njp * 2 + 1][1] = r[3];
                }
#pragma unroll
                for (int nt = 0; nt < 8; nt++)
                    mma16816h(oacc[nt], pf[ks], bf[nt]);
            }
        }
        // no trailing barrier: double buffer spans two stages.
    }

    // ---- finalize ----
    float inv[2];
#pragma unroll
    for (int h2 = 0; h2 < 2; h2++) {
        float l = lrow[h2];
        l += __shfl_xor_sync(0xffffffffu, l, 1);
        l += __shfl_xor_sync(0xffffffffu, l, 2);
        inv[h2] = 1.f / l;
    }
    const int b = bh >> 4;
    const int h = bh & 15;
#pragma unroll
    for (int nt = 0; nt < 8; nt++) {
#pragma unroll
        for (int half = 0; half < 2; half++) {
            const int gi = i0 + wid * 16 + r0 + half * 8;
            const int d0 = nt * 8 + (lane & 3) * 2;
            const float v0 = oacc[nt][half * 2 + 0] * inv[half];
            const float v1 = oacc[nt][half * 2 + 1] * inv[half];
            const size_t idx = ((size_t)(b * SEQ + gi)) * D_MODEL + h * HEAD_DIM + d0;
            *(__half2*)&Oa[idx] = __floats2half2_rn(v0, v1);
        }
    }
}

// ---------------------------------------------------------------------------
__global__ void __launch_bounds__(256) cvt_kernel(
    const float4* __restrict__ in0, const float4* __restrict__ in1,
    const float4* __restrict__ in2,
    __half2* __restrict__ o0, __half2* __restrict__ o1,
    __half2* __restrict__ o2, int n4)
{
    const float4* in = (blockIdx.z == 0) ? in0 : (blockIdx.z == 1) ? in1 : in2;
    __half2* out = (blockIdx.z == 0) ? o0 : (blockIdx.z == 1) ? o1 : o2;
    const int stride = gridDim.x * blockDim.x;
    for (int i = blockIdx.x * blockDim.x + threadIdx.x; i < n4; i += stride) {
        float4 v = in[i];
        out[i * 2 + 0] = __floats2half2_rn(v.x, v.y);
        out[i * 2 + 1] = __floats2half2_rn(v.z, v.w);
    }
}

__global__ void __launch_bounds__(256) wt_kernel(
    const float* __restrict__ W0, const float* __restrict__ W1,
    const float* __restrict__ W2, const float* __restrict__ W3,
    __half* __restrict__ T0, __half* __restrict__ T1,
    __half* __restrict__ T2, __half* __restrict__ T3)
{
    const int z = blockIdx.z;
    const float* W = (z == 0) ? W0 : (z == 1) ? W1 : (z == 2) ? W2 : W3;
    __half* Wt = (z == 0) ? T0 : (z == 1) ? T1 : (z == 2) ? T2 : T3;

    __shared__ float t[32][33];
    const int n0 = blockIdx.x * 32, k0 = blockIdx.y * 32;
    const int tx = threadIdx.x & 31, ty = threadIdx.x >> 5;
#pragma unroll
    for (int r = 0; r < 4; r++) {
        const int kl = ty + r * 8;
        t[kl][tx] = W[(size_t)(k0 + kl) * D_MODEL + n0 + tx];
    }
    __syncthreads();
#pragma unroll
    for (int r = 0; r < 4; r++) {
        const int nl = ty + r * 8;
        Wt[(size_t)(n0 + nl) * D_MODEL + k0 + tx] = __float2half_rn(t[tx][nl]);
    }
}

// ---------------------------------------------------------------------------
extern "C" void kernel_launch(void* const* d_in, const int* in_sizes, int n_in,
                              void* d_out, int out_size)
{
    const float* q  = (const float*)d_in[0];
    const float* k  = (const float*)d_in[1];
    const float* v  = (const float*)d_in[2];
    const float* Wq = (const float*)d_in[3];
    const float* bq = (const float*)d_in[4];
    const float* Wk = (const float*)d_in[5];
    const float* bk = (const float*)d_in[6];
    const float* Wv = (const float*)d_in[7];
    const float* bv = (const float*)d_in[8];
    const float* Wo = (const float*)d_in[9];
    const float* bo = (const float*)d_in[10];

    __half *q16, *k16, *v16, *af, *Q16, *K16, *V16;
    __half *wq, *wk, *wv, *wo;
    cudaGetSymbolAddress((void**)&q16, g_q16);
    cudaGetSymbolAddress((void**)&k16, g_k16);
    cudaGetSymbolAddress((void**)&v16, g_v16);
    cudaGetSymbolAddress((void**)&af, g_af);
    cudaGetSymbolAddress((void**)&Q16, g_Q16);
    cudaGetSymbolAddress((void**)&K16, g_K16);
    cudaGetSymbolAddress((void**)&V16, g_V16);
    cudaGetSymbolAddress((void**)&wq, g_Wq16);
    cudaGetSymbolAddress((void**)&wk, g_Wk16);
    cudaGetSymbolAddress((void**)&wv, g_Wv16);
    cudaGetSymbolAddress((void**)&wo, g_Wo16);

    cudaFuncSetAttribute(flash_kernel,
                         cudaFuncAttributeMaxDynamicSharedMemorySize, FLASH_SMEM);
    cudaFuncSetAttribute(gemm_mma_kernel<0>,
                         cudaFuncAttributeMaxDynamicSharedMemorySize, G4_SMEM);
    cudaFuncSetAttribute(gemm_mma_kernel<1>,
                         cudaFuncAttributeMaxDynamicSharedMemorySize, G4_SMEM);

    wt_kernel<<<dim3(32, 32, 4), 256>>>(Wq, Wk, Wv, Wo, wq, wk, wv, wo);

    const int n4 = MROWS * D_MODEL / 4;
    cvt_kernel<<<dim3(1024, 1, 3), 256>>>(
        (const float4*)q, (const float4*)k, (const float4*)v,
        (__half2*)q16, (__half2*)k16, (__half2*)v16, n4);

    // Fused QKV projections -> single fp16 heads layout (Q scaled log2e/32)
    dim3 gQKV(GN / 128, MROWS / 128, 3);
    gemm_mma_kernel<1><<<gQKV, 256, G4_SMEM>>>(
        q16, k16, v16,
        wq, wk, wv,
        bq, bk, bv,
        Q16, K16, V16,
        nullptr);

    flash_kernel<<<dim3(SEQ / 128, BH), 256, FLASH_SMEM>>>(Q16, K16, V16, af);

    // Output projection -> fp32 d_out
    dim3 gO(GN / 128, MROWS / 128, 1);
    gemm_mma_kernel<0><<<gO, 256, G4_SMEM>>>(
        af, nullptr, nullptr,
        wo, nullptr, nullptr,
        bo, nullptr, nullptr,
        nullptr, nullptr, nullptr,
        (float*)d_out);
}

// round 17
// speedup vs baseline: 1.0435x; 1.0435x over previous
#include <cuda_runtime.h>
#include <cuda_bf16.h>
#include <cuda_fp16.h>
#include <cstdint>

#define D_MODEL 1024
#define N_HEAD  16
#define HEAD_DIM 64
#define BATCH   4
#define SEQ     2048
#define BH      (BATCH * N_HEAD)          // 64
#define MROWS   (BATCH * SEQ)             // 8192
#define GK      1024
#define GN      1024

// ---------------------------------------------------------------------------
// Scratch (device globals)
// ---------------------------------------------------------------------------
__device__ __half g_q16[MROWS * D_MODEL], g_k16[MROWS * D_MODEL], g_v16[MROWS * D_MODEL];
__device__ __half g_af[MROWS * D_MODEL];     // flash output, fp16
// projected Q/K/V single fp16, heads layout [bh][s][hd]
// (Q pre-scaled by log2(e)/32 -> scores are base-2 logits)
__device__ __half g_Q16[BH * SEQ * HEAD_DIM], g_K16[BH * SEQ * HEAD_DIM];
__device__ __half g_V16[BH * SEQ * HEAD_DIM];
// transposed weights [N][K], single fp16
__device__ __half g_Wq16[D_MODEL * D_MODEL], g_Wk16[D_MODEL * D_MODEL];
__device__ __half g_Wv16[D_MODEL * D_MODEL], g_Wo16[D_MODEL * D_MODEL];

// ---------------------------------------------------------------------------
__device__ __forceinline__ uint32_t smem_u32(const void* p) {
    uint32_t a;
    asm("{ .reg .u64 t; cvta.to.shared.u64 t, %1; cvt.u32.u64 %0, t; }"
        : "=r"(a) : "l"(p));
    return a;
}

#define CP_ASYNC16(dst_u32, src_ptr) \
    asm volatile("cp.async.cg.shared.global [%0], [%1], 16;" \
        :: "r"(dst_u32), "l"(src_ptr))

__device__ __forceinline__ void ldsm_x4(uint32_t* r, uint32_t addr) {
    asm volatile("ldmatrix.sync.aligned.m8n8.x4.shared.b16 {%0,%1,%2,%3}, [%4];"
        : "=r"(r[0]), "=r"(r[1]), "=r"(r[2]), "=r"(r[3]) : "r"(addr));
}

__device__ __forceinline__ void ldsm_x4_t(uint32_t* r, uint32_t addr) {
    asm volatile("ldmatrix.sync.aligned.m8n8.x4.trans.shared.b16 {%0,%1,%2,%3}, [%4];"
        : "=r"(r[0]), "=r"(r[1]), "=r"(r[2]), "=r"(r[3]) : "r"(addr));
}

__device__ __forceinline__ void mma16816h(float* d, const uint32_t* a,
                                          const uint32_t* b) {
    asm volatile(
        "mma.sync.aligned.m16n8k16.row.col.f32.f16.f16.f32 "
        "{%0,%1,%2,%3}, {%4,%5,%6,%7}, {%8,%9}, {%0,%1,%2,%3};"
        : "+f"(d[0]), "+f"(d[1]), "+f"(d[2]), "+f"(d[3])
        : "r"(a[0]), "r"(a[1]), "r"(a[2]), "r"(a[3]), "r"(b[0]), "r"(b[1]));
}

__device__ __forceinline__ uint32_t ex2_f16x2(uint32_t x) {
    uint32_t r;
    asm("ex2.approx.f16x2 %0, %1;" : "=r"(r) : "r"(x));
    return r;
}

// ---------------------------------------------------------------------------
// fp16 single-term GEMM: C = A * W + bias.  256 threads, BM=128 BN=128 BK=32,
// 4-stage cp.async pipeline, 81.9 KB smem -> 2 CTAs/SM.
// Round-14 loop structure (issue-before-wait; two barriers) — fastest measured.
// MODE 1: single fp16 heads layout out (z==0 scales by log2e/32).
// MODE 0: fp32 row-major out.
// ---------------------------------------------------------------------------
#define NSLABS  32
#define S_A     (128 * 40)
#define S_ST    (2 * S_A)
#define G4_SMEM (4 * S_ST * 2)            // 81920

template <int MODE>
__global__ void __launch_bounds__(256) gemm_mma_kernel(
    const __half* __restrict__ A0, const __half* __restrict__ A1,
    const __half* __restrict__ A2,
    const __half* __restrict__ B0, const __half* __restrict__ B1,
    const __half* __restrict__ B2,
    const float* __restrict__ bias0, const float* __restrict__ bias1,
    const float* __restrict__ bias2,
    __half* __restrict__ O0, __half* __restrict__ O1,
    __half* __restrict__ O2,
    float* __restrict__ out32)
{
    extern __shared__ __half gsm[];

    const int z = blockIdx.z;
    const __half* Ag = (z == 0) ? A0 : (z == 1) ? A1 : A2;
    const __half* Bg = (z == 0) ? B0 : (z == 1) ? B1 : B2;
    const float* bias = (z == 0) ? bias0 : (z == 1) ? bias1 : bias2;
    __half* outp = (z == 0) ? O0 : (z == 1) ? O1 : O2;
    const float oscale = (MODE == 1 && z == 0) ? 0.03125f * 1.4426950408889634f
                                               : 1.0f;

    const int tid = threadIdx.x;
    const int wid = tid >> 5;
    const int lane = tid & 31;
    const int m0 = blockIdx.y * 128;
    const int n0 = blockIdx.x * 128;
    const int wm = (wid & 1) * 64;
    const int wn = (wid >> 1) * 32;

    float acc[4][4][4];
#pragma unroll
    for (int i = 0; i < 4; i++)
#pragma unroll
        for (int j = 0; j < 4; j++)
#pragma unroll
            for (int c = 0; c < 4; c++) acc[i][j][c] = 0.f;

    const int ldrow = tid >> 2;
    const int ldcol = (tid & 3) * 8;

    auto issue_load = [&](int stage, int slab) {
        const int k0 = slab << 5;
        __half* sA = gsm + stage * S_ST;
        __half* sB = sA + S_A;
#pragma unroll
        for (int r = 0; r < 2; r++) {
            const int row = ldrow + r * 64;
            const size_t ga = (size_t)(m0 + row) * GK + k0 + ldcol;
            const size_t gb = (size_t)(n0 + row) * GK + k0 + ldcol;
            CP_ASYNC16(smem_u32(&sA[row * 40 + ldcol]), Ag + ga);
            CP_ASYNC16(smem_u32(&sB[row * 40 + ldcol]), Bg + gb);
        }
        asm volatile("cp.async.commit_group;" ::: "memory");
    };

    issue_load(0, 0);
    issue_load(1, 1);
    issue_load(2, 2);

    int st = 0;
    for (int i = 0; i < NSLABS; i++) {
        if (i + 3 < NSLABS) {
            issue_load((st + 3) & 3, i + 3);
            asm volatile("cp.async.wait_group 3;" ::: "memory");
        } else if (i + 2 < NSLABS) {
            asm volatile("cp.async.wait_group 2;" ::: "memory");
        } else if (i + 1 < NSLABS) {
            asm volatile("cp.async.wait_group 1;" ::: "memory");
        } else {
            asm volatile("cp.async.wait_group 0;" ::: "memory");
        }
        __syncthreads();

        const __half* sA = gsm + st * S_ST;
        const __half* sB = sA + S_A;

#pragma unroll
        for (int ks = 0; ks < 2; ks++) {
            uint32_t bf[4][2];
#pragma unroll
            for (int njp = 0; njp < 2; njp++) {
                const int t = lane >> 3;
                const int sof = (wn + njp * 16 + (t >> 1) * 8 + (lane & 7)) * 40 +
                                ks * 16 + (t & 1) * 8;
                uint32_t r[4];
                ldsm_x4(r, smem_u32(&sB[sof]));
                bf[njp * 2 + 0][0] = r[0]; bf[njp * 2 + 0][1] = r[1];
                bf[njp * 2 + 1][0] = r[2]; bf[njp * 2 + 1][1] = r[3];
            }
#pragma unroll
            for (int mi = 0; mi < 4; mi++) {
                uint32_t af[4];
                const int sof = (wm + mi * 16 + (lane & 15)) * 40 +
                                ks * 16 + (lane >> 4) * 8;
                ldsm_x4(af, smem_u32(&sA[sof]));
#pragma unroll
                for (int nj = 0; nj < 4; nj++)
                    mma16816h(acc[mi][nj], af, bf[nj]);
            }
        }
        __syncthreads();
        st = (st + 1) & 3;
    }

#pragma unroll
    for (int mi = 0; mi < 4; mi++) {
#pragma unroll
        for (int nj = 0; nj < 4; nj++) {
            const int n = n0 + wn + nj * 8 + (lane & 3) * 2;
            const float b0 = bias[n], b1 = bias[n + 1];
#pragma unroll
            for (int half = 0; half < 2; half++) {
                const int m = m0 + wm + mi * 16 + (lane >> 2) + half * 8;
                const float v0 = (acc[mi][nj][half * 2 + 0] + b0) * oscale;
                const float v1 = (acc[mi][nj][half * 2 + 1] + b1) * oscale;
                if (MODE == 1) {
                    const int b = m >> 11;
                    const int s = m & (SEQ - 1);
                    const int h = n >> 6;
                    const int d = n & 63;
                    const size_t idx =
                        ((((size_t)b * N_HEAD + h) * SEQ) + s) * HEAD_DIM + d;
                    *(__half2*)&outp[idx] = __floats2half2_rn(v0, v1);
                } else {
                    *(float2*)&out32[(size_t)m * GN + n] = make_float2(v0, v1);
                }
            }
        }
    }
}

// ---------------------------------------------------------------------------
// Fused flash attention (round-15 config — fastest measured: 161.6 us).
// all-fp16, 64-key KV double-buffered cp.async stages, exp2-domain softmax,
// f16x2 EX2 tail, heavy CTAs first, fully-masked-warp skip.
// smem: Q 128x72 + 2 x (K 64x72 + V 64x72) = 55296 B.
// grid (SEQ/128, BH), 256 threads.
// ---------------------------------------------------------------------------
#define FPAD 72
#define KV_ST (2 * 64 * FPAD)            // K+V per stage (elements)
#define FLASH_SMEM ((128 * FPAD + 2 * KV_ST) * 2)   // 55296

__global__ void __launch_bounds__(256) flash_kernel(
    const __half* __restrict__ Qg, const __half* __restrict__ Kg,
    const __half* __restrict__ Vg, __half* __restrict__ Oa)
{
    extern __shared__ __half fsm[];
    __half* sQ = fsm;                        // 128*FPAD
    __half* kvBase = sQ + 128 * FPAD;        // 2 stages of [K 64x72 | V 64x72]

    const int tid = threadIdx.x;
    const int wid = tid >> 5;
    const int lane = tid & 31;
    // reversed order: heavy causal tiles (large i0) first
    const int i0 = (gridDim.x - 1 - blockIdx.x) * 128;
    const int bh = blockIdx.y;
    const size_t base = (size_t)bh * SEQ * HEAD_DIM;

    for (int c = tid; c < 1024; c += 256) {
        const int row = c >> 3, c8 = (c & 7) * 8;
        *(uint4*)&sQ[row * FPAD + c8] =
            *(const uint4*)&Qg[base + (size_t)(i0 + row) * HEAD_DIM + c8];
    }

    const int ldrow = tid >> 2;              // 0..63
    const int ldcb = (tid & 3) * 16;         // 0,16,32,48 (halfs)

    auto issue_kv = [&](int it, int buf) {
        const int kk0 = it * 64;
        __half* sK = kvBase + buf * KV_ST;
        __half* sV = sK + 64 * FPAD;
#pragma unroll
        for (int r = 0; r < 2; r++) {
            const int col = ldcb + r * 8;
            const size_t g = base + (size_t)(kk0 + ldrow) * HEAD_DIM + col;
            CP_ASYNC16(smem_u32(&sK[ldrow * FPAD + col]), Kg + g);
            CP_ASYNC16(smem_u32(&sV[ldrow * FPAD + col]), Vg + g);
        }
        asm volatile("cp.async.commit_group;" ::: "memory");
    };

    float oacc[8][4];
#pragma unroll
    for (int nt = 0; nt < 8; nt++)
#pragma unroll
        for (int c = 0; c < 4; c++) oacc[nt][c] = 0.f;
    float mrow[2] = {-1e30f, -1e30f};
    float lrow[2] = {0.f, 0.f};

    const int r0 = lane >> 2;
    const int nIter = i0 / 64 + 2;

    issue_kv(0, 0);

    for (int it = 0; it < nIter; it++) {
        asm volatile("cp.async.wait_group 0;" ::: "memory");
        __syncthreads();
        if (it + 1 < nIter) issue_kv(it + 1, (it + 1) & 1);

        const int kk0 = it * 64;
        // warp fully masked? (all 16 rows < kk0) -> skip all compute
        if (kk0 > i0 + wid * 16 + 15) continue;

        const __half* sK = kvBase + (it & 1) * KV_ST;
        const __half* sV = sK + 64 * FPAD;

        // ---- S = Q K^T (base-2 logits; Q pre-scaled) ----
        float sacc[8][4];
#pragma unroll
        for (int nt = 0; nt < 8; nt++)
#pragma unroll
            for (int c = 0; c < 4; c++) sacc[nt][c] = 0.f;

#pragma unroll
        for (int ks = 0; ks < 4; ks++) {
            uint32_t af[4];
            const int qof = (wid * 16 + (lane & 15)) * FPAD + ks * 16 + (lane >> 4) * 8;
            ldsm_x4(af, smem_u32(&sQ[qof]));
            uint32_t bf[8][2];
#pragma unroll
            for (int njp = 0; njp < 4; njp++) {
                const int t = lane >> 3;
                const int kof = (njp * 16 + (t >> 1) * 8 + (lane & 7)) * FPAD +
                                ks * 16 + (t & 1) * 8;
                uint32_t r[4];
                ldsm_x4(r, smem_u32(&sK[kof]));
                bf[njp * 2 + 0][0] = r[0]; bf[njp * 2 + 0][1] = r[1];
                bf[njp * 2 + 1][0] = r[2]; bf[njp * 2 + 1][1] = r[3];
            }
#pragma unroll
            for (int nt = 0; nt < 8; nt++)
                mma16816h(sacc[nt], af, bf[nt]);
        }

        // ---- causal mask + running max ----
        const bool domask = (kk0 + 63 > i0 + wid * 16);
        float tmax[2] = {-1e30f, -1e30f};
#pragma unroll
        for (int nt = 0; nt < 8; nt++) {
#pragma unroll
            for (int c = 0; c < 4; c++) {
                float s = sacc[nt][c];
                if (domask) {
                    const int gi = i0 + wid * 16 + r0 + (c >> 1) * 8;
                    const int gj = kk0 + nt * 8 + (lane & 3) * 2 + (c & 1);
                    if (gj > gi) s = -1e30f;
                }
                sacc[nt][c] = s;
                tmax[c >> 1] = fmaxf(tmax[c >> 1], s);
            }
        }
#pragma unroll
        for (int h2 = 0; h2 < 2; h2++) {
            tmax[h2] = fmaxf(tmax[h2], __shfl_xor_sync(0xffffffffu, tmax[h2], 1));
            tmax[h2] = fmaxf(tmax[h2], __shfl_xor_sync(0xffffffffu, tmax[h2], 2));
        }
        float fac[2], mnew[2];
#pragma unroll
        for (int h2 = 0; h2 < 2; h2++) {
            mnew[h2] = fmaxf(mrow[h2], tmax[h2]);
            fac[h2] = exp2f(mrow[h2] - mnew[h2]);
            mrow[h2] = mnew[h2];
            lrow[h2] *= fac[h2];
        }
        if (__any_sync(0xffffffffu, (fac[0] != 1.f) | (fac[1] != 1.f))) {
#pragma unroll
            for (int nt = 0; nt < 8; nt++)
#pragma unroll
                for (int c = 0; c < 4; c++) oacc[nt][c] *= fac[c >> 1];
        }

        // ---- p = exp2(s - mnew): fp32 diff, f16x2 EX2; pf is the PV A-frag ----
        uint32_t pf[4][4];
        __half2 lsum[2];
        lsum[0] = __floats2half2_rn(0.f, 0.f);
        lsum[1] = __floats2half2_rn(0.f, 0.f);
#pragma unroll
        for (int t = 0; t < 4; t++) {
#pragma unroll
            for (int q = 0; q < 4; q++) {
                const int nt = 2 * t + (q >> 1);
                const int hh = q & 1;
                const float da = sacc[nt][hh * 2 + 0] - mnew[hh];
                const float db = sacc[nt][hh * 2 + 1] - mnew[hh];
                const __half2 dh = __floats2half2_rn(da, db);
                const uint32_t ph = ex2_f16x2(*(const uint32_t*)&dh);
                pf[t][q] = ph;
                lsum[hh] = __hadd2(lsum[hh], *(const __half2*)&ph);
            }
        }
#pragma unroll
        for (int h2 = 0; h2 < 2; h2++) {
            const float2 lf = __half22float2(lsum[h2]);
            lrow[h2] += lf.x + lf.y;
        }

        // ---- O += P V ----
#pragma unroll
        for (int ks = 0; ks < 4; ks++) {
            uint32_t bf[8][2];
#pragma unroll
            for (int njp = 0; njp < 4; njp++) {
                const int t = lane >> 3;
                const int vof = (ks * 16 + (t & 1) * 8 + (lane & 7)) * FPAD +
                                njp * 16 + (t >> 1) * 8;
                uint32_t r[4];
                ldsm_x4_t(r, smem_u32(&sV[vof]));
                bf[njp * 2 + 0][0] = r[0]; bf[njp * 2 + 0][1] = r[1];
                bf[njp * 2 + 1][0] = r[2]; bf[njp * 2 + 1][1] = r[3];
            }
#pragma unroll
            for (int nt = 0; nt < 8; nt++)
                mma16816h(oacc[nt], pf[ks], bf[nt]);
        }
        // no trailing barrier: double buffer spans two iterations.
    }

    // ---- finalize ----
    float inv[2];
#pragma unroll
    for (int h2 = 0; h2 < 2; h2++) {
        float l = lrow[h2];
        l += __shfl_xor_sync(0xffffffffu, l, 1);
        l += __shfl_xor_sync(0xffffffffu, l, 2);
        inv[h2] = 1.f / l;
    }
    const int b = bh >> 4;
    const int h = bh & 15;
#pragma unroll
    for (int nt = 0; nt < 8; nt++) {
#pragma unroll
        for (int half = 0; half < 2; half++) {
            const int gi = i0 + wid * 16 + r0 + half * 8;
            const int d0 = nt * 8 + (lane & 3) * 2;
            const float v0 = oacc[nt][half * 2 + 0] * inv[half];
            const float v1 = oacc[nt][half * 2 + 1] * inv[half];
            const size_t idx = ((size_t)(b * SEQ + gi)) * D_MODEL + h * HEAD_DIM + d0;
            *(__half2*)&Oa[idx] = __floats2half2_rn(v0, v1);
        }
    }
}

// ---------------------------------------------------------------------------
__global__ void __launch_bounds__(256) cvt_kernel(
    const float4* __restrict__ in0, const float4* __restrict__ in1,
    const float4* __restrict__ in2,
    __half2* __restrict__ o0, __half2* __restrict__ o1,
    __half2* __restrict__ o2, int n4)
{
    const float4* in = (blockIdx.z == 0) ? in0 : (blockIdx.z == 1) ? in1 : in2;
    __half2* out = (blockIdx.z == 0) ? o0 : (blockIdx.z == 1) ? o1 : o2;
    const int stride = gridDim.x * blockDim.x;
    for (int i = blockIdx.x * blockDim.x + threadIdx.x; i < n4; i += stride) {
        float4 v = in[i];
        out[i * 2 + 0] = __floats2half2_rn(v.x, v.y);
        out[i * 2 + 1] = __floats2half2_rn(v.z, v.w);
    }
}

__global__ void __launch_bounds__(256) wt_kernel(
    const float* __restrict__ W0, const float* __restrict__ W1,
    const float* __restrict__ W2, const float* __restrict__ W3,
    __half* __restrict__ T0, __half* __restrict__ T1,
    __half* __restrict__ T2, __half* __restrict__ T3)
{
    const int z = blockIdx.z;
    const float* W = (z == 0) ? W0 : (z == 1) ? W1 : (z == 2) ? W2 : W3;
    __half* Wt = (z == 0) ? T0 : (z == 1) ? T1 : (z == 2) ? T2 : T3;

    __shared__ float t[32][33];
    const int n0 = blockIdx.x * 32, k0 = blockIdx.y * 32;
    const int tx = threadIdx.x & 31, ty = threadIdx.x >> 5;
#pragma unroll
    for (int r = 0; r < 4; r++) {
        const int kl = ty + r * 8;
        t[kl][tx] = W[(size_t)(k0 + kl) * D_MODEL + n0 + tx];
    }
    __syncthreads();
#pragma unroll
    for (int r = 0; r < 4; r++) {
        const int nl = ty + r * 8;
        Wt[(size_t)(n0 + nl) * D_MODEL + k0 + tx] = __float2half_rn(t[tx][nl]);
    }
}

// ---------------------------------------------------------------------------
extern "C" void kernel_launch(void* const* d_in, const int* in_sizes, int n_in,
                              void* d_out, int out_size)
{
    const float* q  = (const float*)d_in[0];
    const float* k  = (const float*)d_in[1];
    const float* v  = (const float*)d_in[2];
    const float* Wq = (const float*)d_in[3];
    const float* bq = (const float*)d_in[4];
    const float* Wk = (const float*)d_in[5];
    const float* bk = (const float*)d_in[6];
    const float* Wv = (const float*)d_in[7];
    const float* bv = (const float*)d_in[8];
    const float* Wo = (const float*)d_in[9];
    const float* bo = (const float*)d_in[10];

    __half *q16, *k16, *v16, *af, *Q16, *K16, *V16;
    __half *wq, *wk, *wv, *wo;
    cudaGetSymbolAddress((void**)&q16, g_q16);
    cudaGetSymbolAddress((void**)&k16, g_k16);
    cudaGetSymbolAddress((void**)&v16, g_v16);
    cudaGetSymbolAddress((void**)&af, g_af);
    cudaGetSymbolAddress((void**)&Q16, g_Q16);
    cudaGetSymbolAddress((void**)&K16, g_K16);
    cudaGetSymbolAddress((void**)&V16, g_V16);
    cudaGetSymbolAddress((void**)&wq, g_Wq16);
    cudaGetSymbolAddress((void**)&wk, g_Wk16);
    cudaGetSymbolAddress((void**)&wv, g_Wv16);
    cudaGetSymbolAddress((void**)&wo, g_Wo16);

    cudaFuncSetAttribute(flash_kernel,
                         cudaFuncAttributeMaxDynamicSharedMemorySize, FLASH_SMEM);
    cudaFuncSetAttribute(gemm_mma_kernel<0>,
                         cudaFuncAttributeMaxDynamicSharedMemorySize, G4_SMEM);
    cudaFuncSetAttribute(gemm_mma_kernel<1>,
                         cudaFuncAttributeMaxDynamicSharedMemorySize, G4_SMEM);

    wt_kernel<<<dim3(32, 32, 4), 256>>>(Wq, Wk, Wv, Wo, wq, wk, wv, wo);

    const int n4 = MROWS * D_MODEL / 4;
    cvt_kernel<<<dim3(1024, 1, 3), 256>>>(
        (const float4*)q, (const float4*)k, (const float4*)v,
        (__half2*)q16, (__half2*)k16, (__half2*)v16, n4);

    // Fused QKV projections -> single fp16 heads layout (Q scaled log2e/32)
    dim3 gQKV(GN / 128, MROWS / 128, 3);
    gemm_mma_kernel<1><<<gQKV, 256, G4_SMEM>>>(
        q16, k16, v16,
        wq, wk, wv,
        bq, bk, bv,
        Q16, K16, V16,
        nullptr);

    flash_kernel<<<dim3(SEQ / 128, BH), 256, FLASH_SMEM>>>(Q16, K16, V16, af);

    // Output projection -> fp32 d_out
    dim3 gO(GN / 128, MROWS / 128, 1);
    gemm_mma_kernel<0><<<gO, 256, G4_SMEM>>>(
        af, nullptr, nullptr,
        wo, nullptr, nullptr,
        bo, nullptr, nullptr,
        nullptr, nullptr, nullptr,
        (float*)d_out);
}